// round 3
// baseline (speedup 1.0000x reference)
#include <cuda_runtime.h>
#include <math.h>

// ---------------- problem constants ----------------
#define DIMC   384
#define HEADS  12
#define HD     32
#define NTOK   256
#define BATCH  256
#define BHH    (BATCH*HEADS)     // 3072
#define MROWS  (BATCH*NTOK)      // 65536
#define KSZ    5
#define EPSF   1e-6f

// ---------------- scratch (no cudaMalloc allowed) ----------------
// head-major q,k,v: [BH, N, HD] ; att: [M, C]
__device__ float g_q[BHH * NTOK * HD];     // ~100 MB
__device__ float g_k[BHH * NTOK * HD];     // ~100 MB
__device__ float g_v[BHH * NTOK * HD];     // ~100 MB
__device__ float g_att[MROWS * DIMC];      // ~100 MB

// ---------------- GEMM: out[m][j] = sum_k A[m][k] * W[j][k] + bias[j] ----------------
// mode 0: qkv epilogue (relu / pos_enc / scatter into g_q,g_k,g_v head-major)
// mode 1: plain epilogue into o0 ([M, 384])
#define BM 128
#define BN 128
#define BKC 16
#define TM 8
#define TN 8

__global__ __launch_bounds__(256) void gemm_kernel(
    const float* __restrict__ A, const float* __restrict__ Bw,
    const float* __restrict__ bias, const float* __restrict__ pos_enc,
    float* __restrict__ o0, int mode)
{
    __shared__ float As[BKC][BM];
    __shared__ float Bs[BKC][BN];

    const int tid = threadIdx.x;
    const int tx  = tid & 15;
    const int ty  = tid >> 4;
    const int m0  = blockIdx.y * BM;
    const int n0  = blockIdx.x * BN;

    float acc[TM][TN];
#pragma unroll
    for (int i = 0; i < TM; i++)
#pragma unroll
        for (int j = 0; j < TN; j++) acc[i][j] = 0.f;

    for (int k0 = 0; k0 < DIMC; k0 += BKC) {
        // 128x16 tile each for A and B: 512 float4 loads / 256 threads = 2 each
#pragma unroll
        for (int r = 0; r < 2; r++) {
            int idx = tid + r * 256;          // 0..511
            int row = idx >> 2;               // 0..127
            int kq  = (idx & 3) << 2;         // 0,4,8,12
            float4 a4 = __ldg((const float4*)(A + (size_t)(m0 + row) * DIMC + k0 + kq));
            As[kq + 0][row] = a4.x; As[kq + 1][row] = a4.y;
            As[kq + 2][row] = a4.z; As[kq + 3][row] = a4.w;
            float4 b4 = __ldg((const float4*)(Bw + (size_t)(n0 + row) * DIMC + k0 + kq));
            Bs[kq + 0][row] = b4.x; Bs[kq + 1][row] = b4.y;
            Bs[kq + 2][row] = b4.z; Bs[kq + 3][row] = b4.w;
        }
        __syncthreads();

#pragma unroll
        for (int kk = 0; kk < BKC; kk++) {
            float a[TM], b[TN];
            *(float4*)&a[0] = *(const float4*)&As[kk][ty * TM];
            *(float4*)&a[4] = *(const float4*)&As[kk][ty * TM + 4];
            *(float4*)&b[0] = *(const float4*)&Bs[kk][tx * TN];
            *(float4*)&b[4] = *(const float4*)&Bs[kk][tx * TN + 4];
#pragma unroll
            for (int i = 0; i < TM; i++)
#pragma unroll
                for (int j = 0; j < TN; j++)
                    acc[i][j] = fmaf(a[i], b[j], acc[i][j]);
        }
        __syncthreads();
    }

    if (mode == 1) {
        // plain: out[m][j] = acc + bias[j]
#pragma unroll
        for (int i = 0; i < TM; i++) {
            int m = m0 + ty * TM + i;
#pragma unroll
            for (int j4 = 0; j4 < TN; j4 += 4) {
                int j = n0 + tx * TN + j4;
                float4 v;
                v.x = acc[i][j4 + 0] + bias[j + 0];
                v.y = acc[i][j4 + 1] + bias[j + 1];
                v.z = acc[i][j4 + 2] + bias[j + 2];
                v.w = acc[i][j4 + 3] + bias[j + 3];
                *(float4*)(o0 + (size_t)m * DIMC + j) = v;
            }
        }
    } else {
        // qkv: split into q/k/v, relu(q), relu(k+pos_enc), scatter head-major
#pragma unroll
        for (int i = 0; i < TM; i++) {
            int m = m0 + ty * TM + i;
            int b = m >> 8;          // batch (N=256 tokens)
            int n = m & 255;         // token
#pragma unroll
            for (int j = 0; j < TN; j++) {
                int col  = n0 + tx * TN + j;          // 0..1151
                float val = acc[i][j] + bias[col];
                int part = col / DIMC;                // 0=q 1=k 2=v
                int cc   = col - part * DIMC;         // 0..383
                int h    = cc >> 5;
                int c    = cc & 31;
                int idx  = ((b * HEADS + h) * NTOK + n) * HD + c;
                if (part == 0)      g_q[idx] = fmaxf(val, 0.f);
                else if (part == 1) g_k[idx] = fmaxf(val + pos_enc[n * DIMC + cc], 0.f);
                else                g_v[idx] = val;
            }
        }
    }
}

// ---------------- per-head linear attention + depthwise conv ----------------
// one block per (b,h): ksum, kv = k^T v, out_i = z_i * (q_i @ kv) + dwconv5x5(v) + b
// smem floats: ks 256*33, vs 256*33, kvs 32*32, ksum 32, wc 800, bc 32
#define SMEM_ATTN_FLOATS (256*33*2 + 32*32 + 32 + 800 + 32)

__global__ __launch_bounds__(256) void attn_kernel(
    const float* __restrict__ dwc_w, const float* __restrict__ dwc_b)
{
    extern __shared__ float sm[];
    float* ks   = sm;                 // [256][33]
    float* vs   = ks + 256 * 33;      // [256][33]
    float* kvs  = vs + 256 * 33;      // [32][32]
    float* ksum = kvs + 32 * 32;      // [32]
    float* wc   = ksum + 32;          // [32][25]
    float* bc   = wc + 800;           // [32]

    const int head = blockIdx.x;
    const int tid  = threadIdx.x;
    const size_t base = (size_t)head * NTOK * HD;   // 8192 floats

    // load k,v tiles (256x32) into padded smem; 2048 float4 / 256 threads = 8 each
#pragma unroll
    for (int it = 0; it < 8; it++) {
        int idx4 = tid + it * 256;        // 0..2047
        int j    = idx4 >> 3;             // row
        int c4   = (idx4 & 7) << 2;       // col (multiple of 4)
        float4 k4 = *(const float4*)(g_k + base + (size_t)idx4 * 4);
        ks[j * 33 + c4 + 0] = k4.x; ks[j * 33 + c4 + 1] = k4.y;
        ks[j * 33 + c4 + 2] = k4.z; ks[j * 33 + c4 + 3] = k4.w;
        float4 v4 = *(const float4*)(g_v + base + (size_t)idx4 * 4);
        vs[j * 33 + c4 + 0] = v4.x; vs[j * 33 + c4 + 1] = v4.y;
        vs[j * 33 + c4 + 2] = v4.z; vs[j * 33 + c4 + 3] = v4.w;
    }
    for (int i = tid; i < 800; i += 256) wc[i] = dwc_w[i];
    if (tid < 32) bc[tid] = dwc_b[tid];
    __syncthreads();

    // ksum[c] = sum_j k[j][c]
    if (tid < 32) {
        float s = 0.f;
        for (int j = 0; j < NTOK; j++) s += ks[j * 33 + tid];
        ksum[tid] = s;
    }

    // kv[c][d] = sum_j k[j][c] * v[j][d]  (each thread: 1 c, 4 d's)
    {
        int c  = tid >> 3;
        int d0 = (tid & 7) << 2;
        float a0 = 0.f, a1 = 0.f, a2 = 0.f, a3 = 0.f;
        for (int j = 0; j < NTOK; j++) {
            float kc = ks[j * 33 + c];
            const float* vr = vs + j * 33 + d0;
            a0 = fmaf(kc, vr[0], a0);
            a1 = fmaf(kc, vr[1], a1);
            a2 = fmaf(kc, vr[2], a2);
            a3 = fmaf(kc, vr[3], a3);
        }
        kvs[c * 32 + d0 + 0] = a0; kvs[c * 32 + d0 + 1] = a1;
        kvs[c * 32 + d0 + 2] = a2; kvs[c * 32 + d0 + 3] = a3;
    }
    __syncthreads();

    // per-token: z, out = z*(q@kv), + conv(v) + bias
    const int i = tid;               // token index 0..255
    float q[HD];
#pragma unroll
    for (int t = 0; t < 8; t++) {
        float4 q4 = *(const float4*)(g_q + base + (size_t)i * HD + t * 4);
        q[t * 4 + 0] = q4.x; q[t * 4 + 1] = q4.y;
        q[t * 4 + 2] = q4.z; q[t * 4 + 3] = q4.w;
    }

    float zden = EPSF;
#pragma unroll
    for (int c = 0; c < HD; c++) zden = fmaf(q[c], ksum[c], zden);
    float z = 1.f / zden;

    float out[HD];
#pragma unroll
    for (int d = 0; d < HD; d++) out[d] = 0.f;
#pragma unroll
    for (int c = 0; c < HD; c++) {
        float qc = q[c];
        const float* kr = kvs + c * 32;
#pragma unroll
        for (int d = 0; d < HD; d++)
            out[d] = fmaf(qc, kr[d], out[d]);
    }
#pragma unroll
    for (int d = 0; d < HD; d++) out[d] = out[d] * z + bc[d];

    // depthwise 5x5 conv on v; spatial: y = n/16, x = n%16
    const int y = i >> 4, x = i & 15;
#pragma unroll
    for (int dy = -2; dy <= 2; dy++) {
        int yy = y + dy;
        if (yy < 0 || yy > 15) continue;
#pragma unroll
        for (int dx = -2; dx <= 2; dx++) {
            int xx = x + dx;
            if (xx < 0 || xx > 15) continue;
            int j   = yy * 16 + xx;
            int tap = (dy + 2) * 5 + (dx + 2);
            const float* vr = vs + j * 33;
#pragma unroll
            for (int d = 0; d < HD; d++)
                out[d] = fmaf(vr[d], wc[d * 25 + tap], out[d]);
        }
    }

    // write [B,N,C] layout for the proj GEMM
    const int b = head / HEADS, h = head % HEADS;
    float* dst = g_att + ((size_t)(b * NTOK + i)) * DIMC + h * HD;
#pragma unroll
    for (int t = 0; t < 8; t++) {
        float4 v4 = make_float4(out[t * 4 + 0], out[t * 4 + 1],
                                out[t * 4 + 2], out[t * 4 + 3]);
        *(float4*)(dst + t * 4) = v4;
    }
}

// ---------------- launch ----------------
extern "C" void kernel_launch(void* const* d_in, const int* in_sizes, int n_in,
                              void* d_out, int out_size)
{
    const float* x      = (const float*)d_in[0];
    const float* qkv_w  = (const float*)d_in[1];
    const float* qkv_b  = (const float*)d_in[2];
    const float* pos    = (const float*)d_in[3];
    const float* dwc_w  = (const float*)d_in[4];
    const float* dwc_b  = (const float*)d_in[5];
    const float* proj_w = (const float*)d_in[6];
    const float* proj_b = (const float*)d_in[7];
    float* out = (float*)d_out;

    const int smem_attn = SMEM_ATTN_FLOATS * (int)sizeof(float);  // 75,136 B

    // One-time, deterministic setup (kept out of the per-capture path).
    static float* att_ptr = nullptr;
    if (att_ptr == nullptr) {
        cudaGetSymbolAddress((void**)&att_ptr, g_att);
        cudaFuncSetAttribute(attn_kernel,
                             cudaFuncAttributeMaxDynamicSharedMemorySize, smem_attn);
    }

    // 1) qkv = x @ qkv_w^T + b  -> relu/pos -> g_q,g_k,g_v (head-major)
    dim3 g1(3 * DIMC / BN, MROWS / BM);   // (9, 512)
    gemm_kernel<<<g1, 256>>>(x, qkv_w, qkv_b, pos, nullptr, 0);

    // 2) linear attention + depthwise conv -> g_att [M, C]
    attn_kernel<<<BHH, 256, smem_attn>>>(dwc_w, dwc_b);

    // 3) out = g_att @ proj_w^T + proj_b
    dim3 g3(DIMC / BN, MROWS / BM);       // (3, 512)
    gemm_kernel<<<g3, 256>>>(att_ptr, proj_w, proj_b, nullptr, out, 1);
}

// round 6
// speedup vs baseline: 4.0278x; 4.0278x over previous
#include <cuda_runtime.h>
#include <math.h>
#include <stdint.h>

// ---------------- problem constants ----------------
#define DIMC   384
#define HEADS  12
#define HD     32
#define NTOK   256
#define BATCH  256
#define BHH    (BATCH*HEADS)     // 3072
#define MROWS  (BATCH*NTOK)      // 65536
#define EPSF   1e-6f

// ---------------- scratch (no cudaMalloc allowed) ----------------
__device__ float g_q[BHH * NTOK * HD];
__device__ float g_k[BHH * NTOK * HD];
__device__ float g_v[BHH * NTOK * HD];
__device__ float g_att[MROWS * DIMC];

// ================= tf32 tensor-core GEMM =================
// out[m][n] = sum_k A[m][k] * W[n][k] (+bias) ; K = 384
// block tile 128x128x32, 8 warps, warp tile 64x32, mma.m16n8k8.tf32
#define BM 128
#define BN 128
#define BK 32
#define LDT 36                    // padded stride (words): bank = (4r+c)%32, conflict-free
#define TSZ (128*LDT)             // one tile buffer, words
#define KTILES (DIMC/BK)          // 12

__device__ __forceinline__ uint32_t f2tf32(float x) {
    uint32_t y;
    asm volatile("cvt.rna.tf32.f32 %0, %1;" : "=r"(y) : "f"(x));
    return y;
}

__device__ __forceinline__ void cp16(uint32_t saddr, const void* g) {
    asm volatile("cp.async.cg.shared.global [%0], [%1], 16;" :: "r"(saddr), "l"(g));
}

__device__ __forceinline__ void mma_tf32(float* d, const uint32_t* a, const uint32_t* b) {
    asm volatile(
        "mma.sync.aligned.m16n8k8.row.col.f32.tf32.tf32.f32 "
        "{%0,%1,%2,%3}, {%4,%5,%6,%7}, {%8,%9}, {%0,%1,%2,%3};"
        : "+f"(d[0]), "+f"(d[1]), "+f"(d[2]), "+f"(d[3])
        : "r"(a[0]), "r"(a[1]), "r"(a[2]), "r"(a[3]), "r"(b[0]), "r"(b[1]));
}

// mode 0: qkv epilogue (relu / pos_enc / scatter head-major into g_q,g_k,g_v)
// mode 1: plain epilogue (bias) into o0 [M, 384]
__global__ __launch_bounds__(256) void gemm_tc_kernel(
    const float* __restrict__ A, const float* __restrict__ Bw,
    const float* __restrict__ bias, const float* __restrict__ pos_enc,
    float* __restrict__ o0, int mode)
{
    extern __shared__ uint32_t smem[];          // As[2][TSZ], Bs[2][TSZ] = 72 KB
    uint32_t* AsBase = smem;
    uint32_t* BsBase = smem + 2 * TSZ;

    const int tid  = threadIdx.x;
    const int lane = tid & 31;
    const int warp = tid >> 5;
    const int wm   = warp >> 2;                 // 0..1 -> M offset 0/64
    const int wn   = warp & 3;                  // 0..3 -> N offset 0/32/64/96
    const int m0   = blockIdx.y * BM;
    const int n0   = blockIdx.x * BN;
    const int m0w  = wm * 64;
    const int n0w  = wn * 32;
    const int r    = lane >> 2;                 // 0..7
    const int cth  = lane & 3;                  // 0..3

    const uint32_t sA0 = (uint32_t)__cvta_generic_to_shared(AsBase);
    const uint32_t sB0 = (uint32_t)__cvta_generic_to_shared(BsBase);

    float acc[4][4][4];                         // [mt][nt][reg]
#pragma unroll
    for (int mt = 0; mt < 4; mt++)
#pragma unroll
        for (int nt = 0; nt < 4; nt++)
#pragma unroll
            for (int q = 0; q < 4; q++) acc[mt][nt][q] = 0.f;

    // per-thread load indices: 1024 float4 per tile / 256 threads = 4 each
    // idx -> row = idx>>3 (0..127), c4 = (idx&7)*4
    auto issue_tile = [&](int t, int s) {
#pragma unroll
        for (int i = 0; i < 4; i++) {
            int idx = tid + i * 256;
            int row = idx >> 3;
            int c4  = (idx & 7) << 2;
            cp16(sA0 + ((s * TSZ + row * LDT + c4) << 2),
                 A + (size_t)(m0 + row) * DIMC + t * BK + c4);
            cp16(sB0 + ((s * TSZ + row * LDT + c4) << 2),
                 Bw + (size_t)(n0 + row) * DIMC + t * BK + c4);
        }
        asm volatile("cp.async.commit_group;");
    };

    issue_tile(0, 0);

    for (int t = 0; t < KTILES; t++) {
        if (t + 1 < KTILES) {
            issue_tile(t + 1, (t + 1) & 1);
            asm volatile("cp.async.wait_group 1;");
        } else {
            asm volatile("cp.async.wait_group 0;");
        }
        __syncthreads();

        const float* Asf = (const float*)(AsBase + (t & 1) * TSZ);
        const float* Bsf = (const float*)(BsBase + (t & 1) * TSZ);

#pragma unroll
        for (int kk = 0; kk < BK; kk += 8) {
            uint32_t af[4][4], bf[4][2];
#pragma unroll
            for (int mt = 0; mt < 4; mt++) {
                const float* ap = Asf + (m0w + mt * 16 + r) * LDT + kk + cth;
                af[mt][0] = f2tf32(ap[0]);
                af[mt][1] = f2tf32(ap[8 * LDT]);
                af[mt][2] = f2tf32(ap[4]);
                af[mt][3] = f2tf32(ap[8 * LDT + 4]);
            }
#pragma unroll
            for (int nt = 0; nt < 4; nt++) {
                const float* bp = Bsf + (n0w + nt * 8 + r) * LDT + kk + cth;
                bf[nt][0] = f2tf32(bp[0]);
                bf[nt][1] = f2tf32(bp[4]);
            }
#pragma unroll
            for (int mt = 0; mt < 4; mt++)
#pragma unroll
                for (int nt = 0; nt < 4; nt++)
                    mma_tf32(acc[mt][nt], af[mt], bf[nt]);
        }
        __syncthreads();
    }

    // ---------------- epilogue ----------------
    // element map: d0@(mr, cb), d1@(mr, cb+1), d2@(mr+8, cb), d3@(mr+8, cb+1)
    if (mode == 1) {
#pragma unroll
        for (int mt = 0; mt < 4; mt++) {
            int mr = m0 + m0w + mt * 16 + r;
#pragma unroll
            for (int nt = 0; nt < 4; nt++) {
                int cb = n0 + n0w + nt * 8 + cth * 2;
                float2 bv = *(const float2*)(bias + cb);
                float2 v0 = make_float2(acc[mt][nt][0] + bv.x, acc[mt][nt][1] + bv.y);
                float2 v1 = make_float2(acc[mt][nt][2] + bv.x, acc[mt][nt][3] + bv.y);
                *(float2*)(o0 + (size_t)mr * DIMC + cb)       = v0;
                *(float2*)(o0 + (size_t)(mr + 8) * DIMC + cb) = v1;
            }
        }
    } else {
        const int part = n0 / DIMC;                 // whole block in one of q/k/v
#pragma unroll
        for (int mt = 0; mt < 4; mt++) {
#pragma unroll
            for (int rr = 0; rr < 2; rr++) {
                int mr = m0 + m0w + mt * 16 + r + rr * 8;
                int b  = mr >> 8;
                int n  = mr & 255;
#pragma unroll
                for (int nt = 0; nt < 4; nt++) {
                    int col = n0 + n0w + nt * 8 + cth * 2;
                    int cc  = col - part * DIMC;     // 0..383
                    int h   = cc >> 5;
                    int c   = cc & 31;
                    float2 bv = *(const float2*)(bias + col);
                    float v0 = acc[mt][nt][rr * 2 + 0] + bv.x;
                    float v1 = acc[mt][nt][rr * 2 + 1] + bv.y;
                    size_t idx = ((size_t)(b * HEADS + h) * NTOK + n) * HD + c;
                    if (part == 0) {
                        *(float2*)(g_q + idx) = make_float2(fmaxf(v0, 0.f), fmaxf(v1, 0.f));
                    } else if (part == 1) {
                        float2 pv = *(const float2*)(pos_enc + (size_t)n * DIMC + cc);
                        *(float2*)(g_k + idx) =
                            make_float2(fmaxf(v0 + pv.x, 0.f), fmaxf(v1 + pv.y, 0.f));
                    } else {
                        *(float2*)(g_v + idx) = make_float2(v0, v1);
                    }
                }
            }
        }
    }
}

// ---------------- per-head linear attention + depthwise conv ----------------
// one block per (b,h): ksum, kv = k^T v, out_i = z_i*(q_i@kv) + dwconv5x5(v) + b
// smem floats: ks 256*36, vs 256*36, kvs 1024, ksum 32, wc 800, bc 32
#define SMEM_ATTN_FLOATS (256*36*2 + 1024 + 32 + 800 + 32)

__global__ __launch_bounds__(256) void attn_kernel(
    const float* __restrict__ dwc_w, const float* __restrict__ dwc_b)
{
    extern __shared__ float sm[];
    float* ks   = sm;                 // [256][36]
    float* vs   = ks + 256 * 36;      // [256][36]
    float* kvs  = vs + 256 * 36;      // [32][32]
    float* ksum = kvs + 1024;         // [32]
    float* wc   = ksum + 32;          // [32][25]
    float* bc   = wc + 800;           // [32]

    const int head = blockIdx.x;
    const int tid  = threadIdx.x;
    const size_t base = (size_t)head * NTOK * HD;

#pragma unroll
    for (int it = 0; it < 8; it++) {
        int idx4 = tid + it * 256;        // 0..2047
        int j    = idx4 >> 3;
        int c4   = (idx4 & 7) << 2;
        *(float4*)&ks[j * 36 + c4] = *(const float4*)(g_k + base + (size_t)idx4 * 4);
        *(float4*)&vs[j * 36 + c4] = *(const float4*)(g_v + base + (size_t)idx4 * 4);
    }
    for (int i = tid; i < 800; i += 256) wc[i] = dwc_w[i];
    if (tid < 32) bc[tid] = dwc_b[tid];
    __syncthreads();

    if (tid < 32) {
        float s = 0.f;
        for (int j = 0; j < NTOK; j++) s += ks[j * 36 + tid];
        ksum[tid] = s;
    }

    {   // kv[c][d] = sum_j k[j][c] * v[j][d]  (thread: 1 c, 4 d's)
        int c  = tid >> 3;
        int d0 = (tid & 7) << 2;
        float a0 = 0.f, a1 = 0.f, a2 = 0.f, a3 = 0.f;
        for (int j = 0; j < NTOK; j++) {
            float  kc = ks[j * 36 + c];
            float4 v4 = *(const float4*)(vs + j * 36 + d0);
            a0 = fmaf(kc, v4.x, a0);
            a1 = fmaf(kc, v4.y, a1);
            a2 = fmaf(kc, v4.z, a2);
            a3 = fmaf(kc, v4.w, a3);
        }
        kvs[c * 32 + d0 + 0] = a0; kvs[c * 32 + d0 + 1] = a1;
        kvs[c * 32 + d0 + 2] = a2; kvs[c * 32 + d0 + 3] = a3;
    }
    __syncthreads();

    const int i = tid;                // token 0..255
    float q[HD];
#pragma unroll
    for (int t = 0; t < 8; t++) {
        float4 q4 = *(const float4*)(g_q + base + (size_t)i * HD + t * 4);
        q[t * 4 + 0] = q4.x; q[t * 4 + 1] = q4.y;
        q[t * 4 + 2] = q4.z; q[t * 4 + 3] = q4.w;
    }

    float zden = EPSF;
#pragma unroll
    for (int c = 0; c < HD; c++) zden = fmaf(q[c], ksum[c], zden);
    float z = 1.f / zden;

    float out[HD];
#pragma unroll
    for (int d = 0; d < HD; d++) out[d] = 0.f;
#pragma unroll
    for (int c = 0; c < HD; c++) {
        float qc = q[c];
        const float* kr = kvs + c * 32;
#pragma unroll
        for (int d4 = 0; d4 < HD; d4 += 4) {
            float4 k4 = *(const float4*)(kr + d4);
            out[d4 + 0] = fmaf(qc, k4.x, out[d4 + 0]);
            out[d4 + 1] = fmaf(qc, k4.y, out[d4 + 1]);
            out[d4 + 2] = fmaf(qc, k4.z, out[d4 + 2]);
            out[d4 + 3] = fmaf(qc, k4.w, out[d4 + 3]);
        }
    }
#pragma unroll
    for (int d = 0; d < HD; d++) out[d] = out[d] * z + bc[d];

    // depthwise 5x5 conv on v; y = n/16, x = n%16
    const int y = i >> 4, x = i & 15;
#pragma unroll
    for (int dy = -2; dy <= 2; dy++) {
        int yy = y + dy;
        if (yy < 0 || yy > 15) continue;
#pragma unroll
        for (int dx = -2; dx <= 2; dx++) {
            int xx = x + dx;
            if (xx < 0 || xx > 15) continue;
            int j   = yy * 16 + xx;
            int tap = (dy + 2) * 5 + (dx + 2);
            const float* vr = vs + j * 36;
#pragma unroll
            for (int d4 = 0; d4 < HD; d4 += 4) {
                float4 v4 = *(const float4*)(vr + d4);
                out[d4 + 0] = fmaf(v4.x, wc[(d4 + 0) * 25 + tap], out[d4 + 0]);
                out[d4 + 1] = fmaf(v4.y, wc[(d4 + 1) * 25 + tap], out[d4 + 1]);
                out[d4 + 2] = fmaf(v4.z, wc[(d4 + 2) * 25 + tap], out[d4 + 2]);
                out[d4 + 3] = fmaf(v4.w, wc[(d4 + 3) * 25 + tap], out[d4 + 3]);
            }
        }
    }

    const int b = head / HEADS, h = head % HEADS;
    float* dst = g_att + ((size_t)(b * NTOK + i)) * DIMC + h * HD;
#pragma unroll
    for (int t = 0; t < 8; t++)
        *(float4*)(dst + t * 4) = make_float4(out[t*4+0], out[t*4+1], out[t*4+2], out[t*4+3]);
}

// ---------------- launch ----------------
extern "C" void kernel_launch(void* const* d_in, const int* in_sizes, int n_in,
                              void* d_out, int out_size)
{
    const float* x      = (const float*)d_in[0];
    const float* qkv_w  = (const float*)d_in[1];
    const float* qkv_b  = (const float*)d_in[2];
    const float* pos    = (const float*)d_in[3];
    const float* dwc_w  = (const float*)d_in[4];
    const float* dwc_b  = (const float*)d_in[5];
    const float* proj_w = (const float*)d_in[6];
    const float* proj_b = (const float*)d_in[7];
    float* out = (float*)d_out;

    const int smem_gemm = 4 * TSZ * (int)sizeof(uint32_t);          // 73,728 B
    const int smem_attn = SMEM_ATTN_FLOATS * (int)sizeof(float);    // 81,280 B

    static float* att_ptr = nullptr;
    if (att_ptr == nullptr) {
        cudaGetSymbolAddress((void**)&att_ptr, g_att);
        cudaFuncSetAttribute(gemm_tc_kernel,
                             cudaFuncAttributeMaxDynamicSharedMemorySize, smem_gemm);
        cudaFuncSetAttribute(attn_kernel,
                             cudaFuncAttributeMaxDynamicSharedMemorySize, smem_attn);
    }

    // 1) qkv = x @ qkv_w^T + b -> relu/pos -> g_q,g_k,g_v (head-major)
    dim3 g1(3 * DIMC / BN, MROWS / BM);   // (9, 512)
    gemm_tc_kernel<<<g1, 256, smem_gemm>>>(x, qkv_w, qkv_b, pos, nullptr, 0);

    // 2) linear attention + depthwise conv -> g_att [M, C]
    attn_kernel<<<BHH, 256, smem_attn>>>(dwc_w, dwc_b);

    // 3) out = g_att @ proj_w^T + proj_b
    dim3 g3(DIMC / BN, MROWS / BM);       // (3, 512)
    gemm_tc_kernel<<<g3, 256, smem_gemm>>>(att_ptr, proj_w, proj_b, nullptr, out, 1);
}

// round 7
// speedup vs baseline: 4.0599x; 1.0080x over previous
#include <cuda_runtime.h>
#include <math.h>
#include <stdint.h>

// ---------------- problem constants ----------------
#define DIMC   384
#define HEADS  12
#define HD     32
#define NTOK   256
#define BATCH  256
#define BHH    (BATCH*HEADS)     // 3072
#define MROWS  (BATCH*NTOK)      // 65536
#define EPSF   1e-6f

// ---------------- scratch (no cudaMalloc allowed) ----------------
__device__ float g_q[BHH * NTOK * HD];
__device__ float g_k[BHH * NTOK * HD];
__device__ float g_v[BHH * NTOK * HD];
__device__ float g_att[MROWS * DIMC];          // written pre-rounded to tf32
__device__ float g_xr[MROWS * DIMC];           // x pre-rounded to tf32
__device__ float g_wqr[3 * DIMC * DIMC];       // qkv_w pre-rounded
__device__ float g_wpr[DIMC * DIMC];           // proj_w pre-rounded

__device__ __forceinline__ uint32_t f2tf32(float x) {
    uint32_t y;
    asm volatile("cvt.rna.tf32.f32 %0, %1;" : "=r"(y) : "f"(x));
    return y;
}

// ---------------- tf32 pre-round (elementwise, float4) ----------------
__global__ __launch_bounds__(256) void round_tf32_kernel(
    const float* __restrict__ in, float* __restrict__ out, int n4)
{
    int i = blockIdx.x * 256 + threadIdx.x;
    if (i >= n4) return;
    float4 v = ((const float4*)in)[i];
    v.x = __uint_as_float(f2tf32(v.x));
    v.y = __uint_as_float(f2tf32(v.y));
    v.z = __uint_as_float(f2tf32(v.z));
    v.w = __uint_as_float(f2tf32(v.w));
    ((float4*)out)[i] = v;
}

// ================= tf32 tensor-core GEMM =================
// out[m][n] = sum_k A[m][k] * W[n][k] (+bias) ; K = 384
// A and W are PRE-ROUNDED to tf32 bit patterns -> feed mma directly, no cvt.
#define BM 128
#define BN 128
#define BK 32
#define LDT 36                    // padded stride (words): bank = (4r+c)%32, conflict-free
#define TSZ (128*LDT)
#define KTILES (DIMC/BK)          // 12

__device__ __forceinline__ void cp16(uint32_t saddr, const void* g) {
    asm volatile("cp.async.cg.shared.global [%0], [%1], 16;" :: "r"(saddr), "l"(g));
}

__device__ __forceinline__ void mma_tf32(float* d, const uint32_t* a, const uint32_t* b) {
    asm volatile(
        "mma.sync.aligned.m16n8k8.row.col.f32.tf32.tf32.f32 "
        "{%0,%1,%2,%3}, {%4,%5,%6,%7}, {%8,%9}, {%0,%1,%2,%3};"
        : "+f"(d[0]), "+f"(d[1]), "+f"(d[2]), "+f"(d[3])
        : "r"(a[0]), "r"(a[1]), "r"(a[2]), "r"(a[3]), "r"(b[0]), "r"(b[1]));
}

// mode 0: qkv epilogue (relu / pos_enc / scatter head-major into g_q,g_k,g_v)
// mode 1: plain epilogue (bias) into o0 [M, 384]
__global__ __launch_bounds__(256) void gemm_tc_kernel(
    const float* __restrict__ A, const float* __restrict__ Bw,
    const float* __restrict__ bias, const float* __restrict__ pos_enc,
    float* __restrict__ o0, int mode)
{
    extern __shared__ uint32_t smem[];          // As[2][TSZ], Bs[2][TSZ] = 72 KB
    uint32_t* AsBase = smem;
    uint32_t* BsBase = smem + 2 * TSZ;

    const int tid  = threadIdx.x;
    const int lane = tid & 31;
    const int warp = tid >> 5;
    const int wm   = warp >> 2;
    const int wn   = warp & 3;
    const int m0   = blockIdx.y * BM;
    const int n0   = blockIdx.x * BN;
    const int m0w  = wm * 64;
    const int n0w  = wn * 32;
    const int r    = lane >> 2;
    const int cth  = lane & 3;

    const uint32_t sA0 = (uint32_t)__cvta_generic_to_shared(AsBase);
    const uint32_t sB0 = (uint32_t)__cvta_generic_to_shared(BsBase);

    float acc[4][4][4];
#pragma unroll
    for (int mt = 0; mt < 4; mt++)
#pragma unroll
        for (int nt = 0; nt < 4; nt++)
#pragma unroll
            for (int q = 0; q < 4; q++) acc[mt][nt][q] = 0.f;

    auto issue_tile = [&](int t, int s) {
#pragma unroll
        for (int i = 0; i < 4; i++) {
            int idx = tid + i * 256;
            int row = idx >> 3;
            int c4  = (idx & 7) << 2;
            cp16(sA0 + ((s * TSZ + row * LDT + c4) << 2),
                 A + (size_t)(m0 + row) * DIMC + t * BK + c4);
            cp16(sB0 + ((s * TSZ + row * LDT + c4) << 2),
                 Bw + (size_t)(n0 + row) * DIMC + t * BK + c4);
        }
        asm volatile("cp.async.commit_group;");
    };

    issue_tile(0, 0);

    for (int t = 0; t < KTILES; t++) {
        if (t + 1 < KTILES) {
            issue_tile(t + 1, (t + 1) & 1);
            asm volatile("cp.async.wait_group 1;");
        } else {
            asm volatile("cp.async.wait_group 0;");
        }
        __syncthreads();

        const uint32_t* Asu = AsBase + (t & 1) * TSZ;
        const uint32_t* Bsu = BsBase + (t & 1) * TSZ;

#pragma unroll
        for (int kk = 0; kk < BK; kk += 8) {
            uint32_t af[4][4], bf[4][2];
#pragma unroll
            for (int mt = 0; mt < 4; mt++) {
                const uint32_t* ap = Asu + (m0w + mt * 16 + r) * LDT + kk + cth;
                af[mt][0] = ap[0];
                af[mt][1] = ap[8 * LDT];
                af[mt][2] = ap[4];
                af[mt][3] = ap[8 * LDT + 4];
            }
#pragma unroll
            for (int nt = 0; nt < 4; nt++) {
                const uint32_t* bp = Bsu + (n0w + nt * 8 + r) * LDT + kk + cth;
                bf[nt][0] = bp[0];
                bf[nt][1] = bp[4];
            }
#pragma unroll
            for (int mt = 0; mt < 4; mt++)
#pragma unroll
                for (int nt = 0; nt < 4; nt++)
                    mma_tf32(acc[mt][nt], af[mt], bf[nt]);
        }
        __syncthreads();
    }

    // ---------------- epilogue ----------------
    if (mode == 1) {
#pragma unroll
        for (int mt = 0; mt < 4; mt++) {
            int mr = m0 + m0w + mt * 16 + r;
#pragma unroll
            for (int nt = 0; nt < 4; nt++) {
                int cb = n0 + n0w + nt * 8 + cth * 2;
                float2 bv = *(const float2*)(bias + cb);
                float2 v0 = make_float2(acc[mt][nt][0] + bv.x, acc[mt][nt][1] + bv.y);
                float2 v1 = make_float2(acc[mt][nt][2] + bv.x, acc[mt][nt][3] + bv.y);
                *(float2*)(o0 + (size_t)mr * DIMC + cb)       = v0;
                *(float2*)(o0 + (size_t)(mr + 8) * DIMC + cb) = v1;
            }
        }
    } else {
        const int part = n0 / DIMC;
#pragma unroll
        for (int mt = 0; mt < 4; mt++) {
#pragma unroll
            for (int rr = 0; rr < 2; rr++) {
                int mr = m0 + m0w + mt * 16 + r + rr * 8;
                int b  = mr >> 8;
                int n  = mr & 255;
#pragma unroll
                for (int nt = 0; nt < 4; nt++) {
                    int col = n0 + n0w + nt * 8 + cth * 2;
                    int cc  = col - part * DIMC;
                    int h   = cc >> 5;
                    int c   = cc & 31;
                    float2 bv = *(const float2*)(bias + col);
                    float v0 = acc[mt][nt][rr * 2 + 0] + bv.x;
                    float v1 = acc[mt][nt][rr * 2 + 1] + bv.y;
                    size_t idx = ((size_t)(b * HEADS + h) * NTOK + n) * HD + c;
                    if (part == 0) {
                        *(float2*)(g_q + idx) = make_float2(fmaxf(v0, 0.f), fmaxf(v1, 0.f));
                    } else if (part == 1) {
                        float2 pv = *(const float2*)(pos_enc + (size_t)n * DIMC + cc);
                        *(float2*)(g_k + idx) =
                            make_float2(fmaxf(v0 + pv.x, 0.f), fmaxf(v1 + pv.y, 0.f));
                    } else {
                        *(float2*)(g_v + idx) = make_float2(v0, v1);
                    }
                }
            }
        }
    }
}

// ---------------- per-head linear attention + depthwise conv ----------------
#define SMEM_ATTN_FLOATS (256*36*2 + 1024 + 32 + 800 + 32)

__global__ __launch_bounds__(256) void attn_kernel(
    const float* __restrict__ dwc_w, const float* __restrict__ dwc_b)
{
    extern __shared__ float sm[];
    float* ks   = sm;                 // [256][36]
    float* vs   = ks + 256 * 36;      // [256][36]
    float* kvs  = vs + 256 * 36;      // [32][32]
    float* ksum = kvs + 1024;         // [32]
    float* wc   = ksum + 32;          // [32][25]
    float* bc   = wc + 800;           // [32]

    const int head = blockIdx.x;
    const int tid  = threadIdx.x;
    const size_t base = (size_t)head * NTOK * HD;

#pragma unroll
    for (int it = 0; it < 8; it++) {
        int idx4 = tid + it * 256;
        int j    = idx4 >> 3;
        int c4   = (idx4 & 7) << 2;
        *(float4*)&ks[j * 36 + c4] = *(const float4*)(g_k + base + (size_t)idx4 * 4);
        *(float4*)&vs[j * 36 + c4] = *(const float4*)(g_v + base + (size_t)idx4 * 4);
    }
    for (int i = tid; i < 800; i += 256) wc[i] = dwc_w[i];
    if (tid < 32) bc[tid] = dwc_b[tid];
    __syncthreads();

    if (tid < 32) {
        float s = 0.f;
#pragma unroll 4
        for (int j = 0; j < NTOK; j++) s += ks[j * 36 + tid];
        ksum[tid] = s;
    }

    {   // kv[c][d] = sum_j k[j][c] * v[j][d]
        int c  = tid >> 3;
        int d0 = (tid & 7) << 2;
        float a0 = 0.f, a1 = 0.f, a2 = 0.f, a3 = 0.f;
#pragma unroll 4
        for (int j = 0; j < NTOK; j++) {
            float  kc = ks[j * 36 + c];
            float4 v4 = *(const float4*)(vs + j * 36 + d0);
            a0 = fmaf(kc, v4.x, a0);
            a1 = fmaf(kc, v4.y, a1);
            a2 = fmaf(kc, v4.z, a2);
            a3 = fmaf(kc, v4.w, a3);
        }
        kvs[c * 32 + d0 + 0] = a0; kvs[c * 32 + d0 + 1] = a1;
        kvs[c * 32 + d0 + 2] = a2; kvs[c * 32 + d0 + 3] = a3;
    }
    __syncthreads();

    const int i = tid;
    float q[HD];
#pragma unroll
    for (int t = 0; t < 8; t++) {
        float4 q4 = *(const float4*)(g_q + base + (size_t)i * HD + t * 4);
        q[t * 4 + 0] = q4.x; q[t * 4 + 1] = q4.y;
        q[t * 4 + 2] = q4.z; q[t * 4 + 3] = q4.w;
    }

    float zden = EPSF;
#pragma unroll
    for (int c = 0; c < HD; c++) zden = fmaf(q[c], ksum[c], zden);
    float z = 1.f / zden;

    float out[HD];
#pragma unroll
    for (int d = 0; d < HD; d++) out[d] = 0.f;
#pragma unroll
    for (int c = 0; c < HD; c++) {
        float qc = q[c];
        const float* kr = kvs + c * 32;
#pragma unroll
        for (int d4 = 0; d4 < HD; d4 += 4) {
            float4 k4 = *(const float4*)(kr + d4);
            out[d4 + 0] = fmaf(qc, k4.x, out[d4 + 0]);
            out[d4 + 1] = fmaf(qc, k4.y, out[d4 + 1]);
            out[d4 + 2] = fmaf(qc, k4.z, out[d4 + 2]);
            out[d4 + 3] = fmaf(qc, k4.w, out[d4 + 3]);
        }
    }
#pragma unroll
    for (int d = 0; d < HD; d++) out[d] = out[d] * z + bc[d];

    const int y = i >> 4, x = i & 15;
#pragma unroll
    for (int dy = -2; dy <= 2; dy++) {
        int yy = y + dy;
        if (yy < 0 || yy > 15) continue;
#pragma unroll
        for (int dx = -2; dx <= 2; dx++) {
            int xx = x + dx;
            if (xx < 0 || xx > 15) continue;
            int j   = yy * 16 + xx;
            int tap = (dy + 2) * 5 + (dx + 2);
            const float* vr = vs + j * 36;
#pragma unroll
            for (int d4 = 0; d4 < HD; d4 += 4) {
                float4 v4 = *(const float4*)(vr + d4);
                out[d4 + 0] = fmaf(v4.x, wc[(d4 + 0) * 25 + tap], out[d4 + 0]);
                out[d4 + 1] = fmaf(v4.y, wc[(d4 + 1) * 25 + tap], out[d4 + 1]);
                out[d4 + 2] = fmaf(v4.z, wc[(d4 + 2) * 25 + tap], out[d4 + 2]);
                out[d4 + 3] = fmaf(v4.w, wc[(d4 + 3) * 25 + tap], out[d4 + 3]);
            }
        }
    }

    // write [B,N,C] layout PRE-ROUNDED to tf32 (bit-identical to converting in proj GEMM)
    const int b = head / HEADS, h = head % HEADS;
    float* dst = g_att + ((size_t)(b * NTOK + i)) * DIMC + h * HD;
#pragma unroll
    for (int t = 0; t < 8; t++) {
        float4 v4;
        v4.x = __uint_as_float(f2tf32(out[t * 4 + 0]));
        v4.y = __uint_as_float(f2tf32(out[t * 4 + 1]));
        v4.z = __uint_as_float(f2tf32(out[t * 4 + 2]));
        v4.w = __uint_as_float(f2tf32(out[t * 4 + 3]));
        *(float4*)(dst + t * 4) = v4;
    }
}

// ---------------- launch ----------------
extern "C" void kernel_launch(void* const* d_in, const int* in_sizes, int n_in,
                              void* d_out, int out_size)
{
    const float* x      = (const float*)d_in[0];
    const float* qkv_w  = (const float*)d_in[1];
    const float* qkv_b  = (const float*)d_in[2];
    const float* pos    = (const float*)d_in[3];
    const float* dwc_w  = (const float*)d_in[4];
    const float* dwc_b  = (const float*)d_in[5];
    const float* proj_w = (const float*)d_in[6];
    const float* proj_b = (const float*)d_in[7];
    float* out = (float*)d_out;

    const int smem_gemm = 4 * TSZ * (int)sizeof(uint32_t);          // 73,728 B
    const int smem_attn = SMEM_ATTN_FLOATS * (int)sizeof(float);    // 81,280 B

    static float *att_ptr = nullptr, *xr_ptr = nullptr, *wq_ptr = nullptr, *wp_ptr = nullptr;
    if (att_ptr == nullptr) {
        cudaGetSymbolAddress((void**)&att_ptr, g_att);
        cudaGetSymbolAddress((void**)&xr_ptr,  g_xr);
        cudaGetSymbolAddress((void**)&wq_ptr,  g_wqr);
        cudaGetSymbolAddress((void**)&wp_ptr,  g_wpr);
        cudaFuncSetAttribute(gemm_tc_kernel,
                             cudaFuncAttributeMaxDynamicSharedMemorySize, smem_gemm);
        cudaFuncSetAttribute(attn_kernel,
                             cudaFuncAttributeMaxDynamicSharedMemorySize, smem_attn);
    }

    // 0) pre-round A/W operands to tf32 (bit-identical to in-loop cvt)
    {
        int n4x = MROWS * DIMC / 4;
        round_tf32_kernel<<<(n4x + 255) / 256, 256>>>(x, xr_ptr, n4x);
        int n4q = 3 * DIMC * DIMC / 4;
        round_tf32_kernel<<<(n4q + 255) / 256, 256>>>(qkv_w, wq_ptr, n4q);
        int n4p = DIMC * DIMC / 4;
        round_tf32_kernel<<<(n4p + 255) / 256, 256>>>(proj_w, wp_ptr, n4p);
    }

    // 1) qkv = x @ qkv_w^T + b -> relu/pos -> g_q,g_k,g_v (head-major)
    dim3 g1(3 * DIMC / BN, MROWS / BM);   // (9, 512)
    gemm_tc_kernel<<<g1, 256, smem_gemm>>>(xr_ptr, wq_ptr, qkv_b, pos, nullptr, 0);

    // 2) linear attention + depthwise conv -> g_att [M, C] (tf32-rounded)
    attn_kernel<<<BHH, 256, smem_attn>>>(dwc_w, dwc_b);

    // 3) out = g_att @ proj_w^T + proj_b
    dim3 g3(DIMC / BN, MROWS / BM);       // (3, 512)
    gemm_tc_kernel<<<g3, 256, smem_gemm>>>(att_ptr, wp_ptr, proj_b, nullptr, out, 1);
}

// round 8
// speedup vs baseline: 4.7398x; 1.1675x over previous
#include <cuda_runtime.h>
#include <math.h>
#include <stdint.h>

// ---------------- problem constants ----------------
#define DIMC   384
#define HEADS  12
#define HD     32
#define NTOK   256
#define BATCH  256
#define BHH    (BATCH*HEADS)     // 3072
#define MROWS  (BATCH*NTOK)      // 65536
#define EPSF   1e-6f

// ---------------- scratch (no cudaMalloc allowed) ----------------
__device__ float g_q[BHH * NTOK * HD];
__device__ float g_k[BHH * NTOK * HD];
__device__ float g_v[BHH * NTOK * HD];
__device__ float g_att[MROWS * DIMC];          // raw fp32 (proj GEMM cvts in-loop)
__device__ float g_wqr[3 * DIMC * DIMC];       // qkv_w pre-rounded to tf32
__device__ float g_wpr[DIMC * DIMC];           // proj_w pre-rounded to tf32

__device__ __forceinline__ uint32_t f2tf32(float x) {
    uint32_t y;
    asm volatile("cvt.rna.tf32.f32 %0, %1;" : "=r"(y) : "f"(x));
    return y;
}

// ---------------- tf32 pre-round (weights only) ----------------
__global__ __launch_bounds__(256) void round_tf32_kernel(
    const float* __restrict__ in, float* __restrict__ out, int n4)
{
    int i = blockIdx.x * 256 + threadIdx.x;
    if (i >= n4) return;
    float4 v = ((const float4*)in)[i];
    v.x = __uint_as_float(f2tf32(v.x));
    v.y = __uint_as_float(f2tf32(v.y));
    v.z = __uint_as_float(f2tf32(v.z));
    v.w = __uint_as_float(f2tf32(v.w));
    ((float4*)out)[i] = v;
}

// ================= tf32 tensor-core GEMM =================
// out[m][n] = sum_k A[m][k] * W[n][k] (+bias) ; K = 384
// A raw fp32 (cvt.rna per fragment, bit-identical to pre-rounding);
// W pre-rounded tf32 bits, fed to mma directly.
#define BM 128
#define BN 128
#define BK 32
#define LDT 36                    // padded stride (words): conflict-free frag loads
#define TSZ (128*LDT)             // 4608 words per operand-stage
#define KTILES (DIMC/BK)          // 12
#define STAGES 3

__device__ __forceinline__ void cp16(uint32_t saddr, const void* g) {
    asm volatile("cp.async.cg.shared.global [%0], [%1], 16;" :: "r"(saddr), "l"(g));
}

__device__ __forceinline__ void mma_tf32(float* d, const uint32_t* a, const uint32_t* b) {
    asm volatile(
        "mma.sync.aligned.m16n8k8.row.col.f32.tf32.tf32.f32 "
        "{%0,%1,%2,%3}, {%4,%5,%6,%7}, {%8,%9}, {%0,%1,%2,%3};"
        : "+f"(d[0]), "+f"(d[1]), "+f"(d[2]), "+f"(d[3])
        : "r"(a[0]), "r"(a[1]), "r"(a[2]), "r"(a[3]), "r"(b[0]), "r"(b[1]));
}

// mode 0: qkv epilogue (relu / pos_enc / scatter head-major into g_q,g_k,g_v)
// mode 1: plain epilogue (bias) into o0 [M, 384]
__global__ __launch_bounds__(256, 2) void gemm_tc_kernel(
    const float* __restrict__ A, const float* __restrict__ Bw,
    const float* __restrict__ bias, const float* __restrict__ pos_enc,
    float* __restrict__ o0, int mode)
{
    extern __shared__ uint32_t smem[];          // A: 3*TSZ, B: 3*TSZ = 108 KB
    uint32_t* AsBase = smem;
    uint32_t* BsBase = smem + STAGES * TSZ;

    const int tid  = threadIdx.x;
    const int lane = tid & 31;
    const int warp = tid >> 5;
    const int wm   = warp >> 2;
    const int wn   = warp & 3;
    const int m0   = blockIdx.y * BM;
    const int n0   = blockIdx.x * BN;
    const int m0w  = wm * 64;
    const int n0w  = wn * 32;
    const int r    = lane >> 2;
    const int cth  = lane & 3;

    const uint32_t sA0 = (uint32_t)__cvta_generic_to_shared(AsBase);
    const uint32_t sB0 = (uint32_t)__cvta_generic_to_shared(BsBase);

    float acc[4][4][4];
#pragma unroll
    for (int mt = 0; mt < 4; mt++)
#pragma unroll
        for (int nt = 0; nt < 4; nt++)
#pragma unroll
            for (int q = 0; q < 4; q++) acc[mt][nt][q] = 0.f;

    auto issue_tile = [&](int t, int s) {
#pragma unroll
        for (int i = 0; i < 4; i++) {
            int idx = tid + i * 256;
            int row = idx >> 3;
            int c4  = (idx & 7) << 2;
            cp16(sA0 + ((s * TSZ + row * LDT + c4) << 2),
                 A + (size_t)(m0 + row) * DIMC + t * BK + c4);
            cp16(sB0 + ((s * TSZ + row * LDT + c4) << 2),
                 Bw + (size_t)(n0 + row) * DIMC + t * BK + c4);
        }
        asm volatile("cp.async.commit_group;");
    };

    issue_tile(0, 0);
    issue_tile(1, 1);

    for (int t = 0; t < KTILES; t++) {
        if (t + 2 < KTILES) {
            asm volatile("cp.async.wait_group 1;");   // group t complete
        } else {
            asm volatile("cp.async.wait_group 0;");
        }
        __syncthreads();                              // single barrier per iter
        if (t + 2 < KTILES) issue_tile(t + 2, (t + 2) % STAGES);  // stage consumed at t-1

        const int s = t % STAGES;
        const float*    Asf = (const float*)(AsBase + s * TSZ);
        const uint32_t* Bsu = BsBase + s * TSZ;

#pragma unroll
        for (int kk = 0; kk < BK; kk += 8) {
            uint32_t af[4][4], bf[4][2];
#pragma unroll
            for (int mt = 0; mt < 4; mt++) {
                const float* ap = Asf + (m0w + mt * 16 + r) * LDT + kk + cth;
                af[mt][0] = f2tf32(ap[0]);
                af[mt][1] = f2tf32(ap[8 * LDT]);
                af[mt][2] = f2tf32(ap[4]);
                af[mt][3] = f2tf32(ap[8 * LDT + 4]);
            }
#pragma unroll
            for (int nt = 0; nt < 4; nt++) {
                const uint32_t* bp = Bsu + (n0w + nt * 8 + r) * LDT + kk + cth;
                bf[nt][0] = bp[0];
                bf[nt][1] = bp[4];
            }
#pragma unroll
            for (int mt = 0; mt < 4; mt++)
#pragma unroll
                for (int nt = 0; nt < 4; nt++)
                    mma_tf32(acc[mt][nt], af[mt], bf[nt]);
        }
    }

    // ---------------- epilogue ----------------
    if (mode == 1) {
#pragma unroll
        for (int mt = 0; mt < 4; mt++) {
            int mr = m0 + m0w + mt * 16 + r;
#pragma unroll
            for (int nt = 0; nt < 4; nt++) {
                int cb = n0 + n0w + nt * 8 + cth * 2;
                float2 bv = *(const float2*)(bias + cb);
                float2 v0 = make_float2(acc[mt][nt][0] + bv.x, acc[mt][nt][1] + bv.y);
                float2 v1 = make_float2(acc[mt][nt][2] + bv.x, acc[mt][nt][3] + bv.y);
                *(float2*)(o0 + (size_t)mr * DIMC + cb)       = v0;
                *(float2*)(o0 + (size_t)(mr + 8) * DIMC + cb) = v1;
            }
        }
    } else {
        const int part = n0 / DIMC;
#pragma unroll
        for (int mt = 0; mt < 4; mt++) {
#pragma unroll
            for (int rr = 0; rr < 2; rr++) {
                int mr = m0 + m0w + mt * 16 + r + rr * 8;
                int b  = mr >> 8;
                int n  = mr & 255;
#pragma unroll
                for (int nt = 0; nt < 4; nt++) {
                    int col = n0 + n0w + nt * 8 + cth * 2;
                    int cc  = col - part * DIMC;
                    int h   = cc >> 5;
                    int c   = cc & 31;
                    float2 bv = *(const float2*)(bias + col);
                    float v0 = acc[mt][nt][rr * 2 + 0] + bv.x;
                    float v1 = acc[mt][nt][rr * 2 + 1] + bv.y;
                    size_t idx = ((size_t)(b * HEADS + h) * NTOK + n) * HD + c;
                    if (part == 0) {
                        *(float2*)(g_q + idx) = make_float2(fmaxf(v0, 0.f), fmaxf(v1, 0.f));
                    } else if (part == 1) {
                        float2 pv = *(const float2*)(pos_enc + (size_t)n * DIMC + cc);
                        *(float2*)(g_k + idx) =
                            make_float2(fmaxf(v0 + pv.x, 0.f), fmaxf(v1 + pv.y, 0.f));
                    } else {
                        *(float2*)(g_v + idx) = make_float2(v0, v1);
                    }
                }
            }
        }
    }
}

// ---------------- per-head linear attention + depthwise conv ----------------
// smem floats: ks 256*36, vs 256*36, kvp 4*32*36, ksump 256, ksum 32, wc 800, bc 32
#define KVP_LD 36
#define SMEM_ATTN_FLOATS (256*36*2 + 4*32*KVP_LD + 256 + 32 + 800 + 32)

__global__ __launch_bounds__(256, 2) void attn_kernel(
    const float* __restrict__ dwc_w, const float* __restrict__ dwc_b)
{
    extern __shared__ float sm[];
    float* ks    = sm;                      // [256][36] (k matrix; later reused for att partial)
    float* vs    = ks + 256 * 36;           // [256][36]
    float* kvp   = vs + 256 * 36;           // [4][32][KVP_LD] partials; final in kvp[0]
    float* ksump = kvp + 4 * 32 * KVP_LD;   // [8][32]
    float* ksum  = ksump + 256;             // [32]
    float* wc    = ksum + 32;               // [32][25]
    float* bc    = wc + 800;                // [32]

    const int head = blockIdx.x;
    const int tid  = threadIdx.x;
    const size_t base = (size_t)head * NTOK * HD;

    // ---- P1: load k, v, weights ----
#pragma unroll
    for (int it = 0; it < 8; it++) {
        int idx4 = tid + it * 256;
        int j    = idx4 >> 3;
        int c4   = (idx4 & 7) << 2;
        *(float4*)&ks[j * 36 + c4] = *(const float4*)(g_k + base + (size_t)idx4 * 4);
        *(float4*)&vs[j * 36 + c4] = *(const float4*)(g_v + base + (size_t)idx4 * 4);
    }
    for (int i = tid; i < 800; i += 256) wc[i] = dwc_w[i];
    if (tid < 32) bc[tid] = dwc_b[tid];
    __syncthreads();

    // ---- P2: ksum partials (8-way) + kv partials (4 j-groups, 4c x 4d per thread) ----
    {
        int c = tid & 31, g = tid >> 5;
        float s = 0.f;
#pragma unroll 8
        for (int jj = 0; jj < 32; jj++) s += ks[(g * 32 + jj) * 36 + c];
        ksump[g * 32 + c] = s;
    }
    {
        const int jg = tid >> 6;            // 0..3
        const int rm = tid & 63;
        const int c0 = (rm >> 3) * 4;       // 0,4,..28
        const int d0 = (rm & 7) * 4;        // 0,4,..28
        float a[4][4];
#pragma unroll
        for (int ci = 0; ci < 4; ci++)
#pragma unroll
            for (int dj = 0; dj < 4; dj++) a[ci][dj] = 0.f;
        const int jbase = jg * 64;
#pragma unroll 4
        for (int jj = 0; jj < 64; jj++) {
            int j = jbase + jj;
            float4 k4 = *(const float4*)(ks + j * 36 + c0);
            float4 v4 = *(const float4*)(vs + j * 36 + d0);
            a[0][0] = fmaf(k4.x, v4.x, a[0][0]); a[0][1] = fmaf(k4.x, v4.y, a[0][1]);
            a[0][2] = fmaf(k4.x, v4.z, a[0][2]); a[0][3] = fmaf(k4.x, v4.w, a[0][3]);
            a[1][0] = fmaf(k4.y, v4.x, a[1][0]); a[1][1] = fmaf(k4.y, v4.y, a[1][1]);
            a[1][2] = fmaf(k4.y, v4.z, a[1][2]); a[1][3] = fmaf(k4.y, v4.w, a[1][3]);
            a[2][0] = fmaf(k4.z, v4.x, a[2][0]); a[2][1] = fmaf(k4.z, v4.y, a[2][1]);
            a[2][2] = fmaf(k4.z, v4.z, a[2][2]); a[2][3] = fmaf(k4.z, v4.w, a[2][3]);
            a[3][0] = fmaf(k4.w, v4.x, a[3][0]); a[3][1] = fmaf(k4.w, v4.y, a[3][1]);
            a[3][2] = fmaf(k4.w, v4.z, a[3][2]); a[3][3] = fmaf(k4.w, v4.w, a[3][3]);
        }
        float* pb = kvp + jg * 32 * KVP_LD;
#pragma unroll
        for (int ci = 0; ci < 4; ci++)
            *(float4*)(pb + (c0 + ci) * KVP_LD + d0) =
                make_float4(a[ci][0], a[ci][1], a[ci][2], a[ci][3]);
    }
    __syncthreads();

    // ---- P3: reduce ksum + kv ----
    if (tid < 32) {
        float s = 0.f;
#pragma unroll
        for (int g = 0; g < 8; g++) s += ksump[g * 32 + tid];
        ksum[tid] = s;
    }
    {
        int c  = tid >> 3;
        int d0 = (tid & 7) * 4;
        int off = c * KVP_LD + d0;
        float4 s0 = *(const float4*)(kvp + off);
        float4 s1 = *(const float4*)(kvp + 32 * KVP_LD + off);
        float4 s2 = *(const float4*)(kvp + 64 * KVP_LD + off);
        float4 s3 = *(const float4*)(kvp + 96 * KVP_LD + off);
        s0.x += s1.x + s2.x + s3.x;
        s0.y += s1.y + s2.y + s3.y;
        s0.z += s1.z + s2.z + s3.z;
        s0.w += s1.w + s2.w + s3.w;
        *(float4*)(kvp + off) = s0;
    }
    __syncthreads();

    // ---- P4: per-token z * (q @ kv) -> stash into ks region ----
    {
        const int i = tid;
        float q[HD];
#pragma unroll
        for (int t = 0; t < 8; t++) {
            float4 q4 = *(const float4*)(g_q + base + (size_t)i * HD + t * 4);
            q[t * 4 + 0] = q4.x; q[t * 4 + 1] = q4.y;
            q[t * 4 + 2] = q4.z; q[t * 4 + 3] = q4.w;
        }
        float zden = EPSF;
#pragma unroll
        for (int c = 0; c < HD; c++) zden = fmaf(q[c], ksum[c], zden);
        float z = 1.f / zden;

        float out[HD];
#pragma unroll
        for (int d = 0; d < HD; d++) out[d] = 0.f;
#pragma unroll
        for (int c = 0; c < HD; c++) {
            float qc = q[c];
            const float* kr = kvp + c * KVP_LD;
#pragma unroll
            for (int d4 = 0; d4 < HD; d4 += 4) {
                float4 k4 = *(const float4*)(kr + d4);
                out[d4 + 0] = fmaf(qc, k4.x, out[d4 + 0]);
                out[d4 + 1] = fmaf(qc, k4.y, out[d4 + 1]);
                out[d4 + 2] = fmaf(qc, k4.z, out[d4 + 2]);
                out[d4 + 3] = fmaf(qc, k4.w, out[d4 + 3]);
            }
        }
        // ks region is dead (k consumed in P2); reuse as att staging [256][36]
#pragma unroll
        for (int t = 0; t < 8; t++)
            *(float4*)(ks + i * 36 + t * 4) =
                make_float4(out[t*4+0]*z, out[t*4+1]*z, out[t*4+2]*z, out[t*4+3]*z);
    }
    __syncthreads();

    // ---- P5: depthwise 5x5 conv (thread = 4 tokens x 8 channels) + combine + store ----
    {
        const int tg = tid >> 2;            // 0..63
        const int dg = tid & 3;             // 0..3
        const int d0 = dg * 8;
        const int y  = tg >> 2;             // 0..15
        const int x0 = (tg & 3) * 4;        // 0,4,8,12

        float acc[4][8];
#pragma unroll
        for (int xi = 0; xi < 4; xi++)
#pragma unroll
            for (int dd = 0; dd < 8; dd++) acc[xi][dd] = 0.f;

#pragma unroll
        for (int dy = -2; dy <= 2; dy++) {
            int yy = y + dy;
            if (yy < 0 || yy > 15) continue;
            float w[5][8];
#pragma unroll
            for (int dxi = 0; dxi < 5; dxi++)
#pragma unroll
                for (int dd = 0; dd < 8; dd++)
                    w[dxi][dd] = wc[(d0 + dd) * 25 + (dy + 2) * 5 + dxi];
#pragma unroll
            for (int xo = -2; xo <= 5; xo++) {
                int xx = x0 + xo;
                if (xx < 0 || xx > 15) continue;
                const float* vr = vs + (yy * 16 + xx) * 36 + d0;
                float4 va = *(const float4*)vr;
                float4 vb = *(const float4*)(vr + 4);
                float v8[8] = {va.x, va.y, va.z, va.w, vb.x, vb.y, vb.z, vb.w};
#pragma unroll
                for (int dxi = 0; dxi < 5; dxi++) {
                    int xi = xo - (dxi - 2);     // token offset s.t. x0+xi+dx == xx
                    if (xi < 0 || xi > 3) continue;
#pragma unroll
                    for (int dd = 0; dd < 8; dd++)
                        acc[xi][dd] = fmaf(v8[dd], w[dxi][dd], acc[xi][dd]);
                }
            }
        }

        const int b = head / HEADS, h = head % HEADS;
#pragma unroll
        for (int xi = 0; xi < 4; xi++) {
            int n = y * 16 + x0 + xi;
            const float* as = ks + n * 36 + d0;
            float4 r0, r1;
            r0.x = as[0] + acc[xi][0] + bc[d0 + 0];
            r0.y = as[1] + acc[xi][1] + bc[d0 + 1];
            r0.z = as[2] + acc[xi][2] + bc[d0 + 2];
            r0.w = as[3] + acc[xi][3] + bc[d0 + 3];
            r1.x = as[4] + acc[xi][4] + bc[d0 + 4];
            r1.y = as[5] + acc[xi][5] + bc[d0 + 5];
            r1.z = as[6] + acc[xi][6] + bc[d0 + 6];
            r1.w = as[7] + acc[xi][7] + bc[d0 + 7];
            float* dst = g_att + ((size_t)(b * NTOK + n)) * DIMC + h * HD + d0;
            *(float4*)dst       = r0;
            *(float4*)(dst + 4) = r1;
        }
    }
}

// ---------------- launch ----------------
extern "C" void kernel_launch(void* const* d_in, const int* in_sizes, int n_in,
                              void* d_out, int out_size)
{
    const float* x      = (const float*)d_in[0];
    const float* qkv_w  = (const float*)d_in[1];
    const float* qkv_b  = (const float*)d_in[2];
    const float* pos    = (const float*)d_in[3];
    const float* dwc_w  = (const float*)d_in[4];
    const float* dwc_b  = (const float*)d_in[5];
    const float* proj_w = (const float*)d_in[6];
    const float* proj_b = (const float*)d_in[7];
    float* out = (float*)d_out;

    const int smem_gemm = 2 * STAGES * TSZ * (int)sizeof(uint32_t);   // 110,592 B
    const int smem_attn = SMEM_ATTN_FLOATS * (int)sizeof(float);      // ~96,640 B

    static float *att_ptr = nullptr, *wq_ptr = nullptr, *wp_ptr = nullptr;
    if (att_ptr == nullptr) {
        cudaGetSymbolAddress((void**)&att_ptr, g_att);
        cudaGetSymbolAddress((void**)&wq_ptr,  g_wqr);
        cudaGetSymbolAddress((void**)&wp_ptr,  g_wpr);
        cudaFuncSetAttribute(gemm_tc_kernel,
                             cudaFuncAttributeMaxDynamicSharedMemorySize, smem_gemm);
        cudaFuncSetAttribute(attn_kernel,
                             cudaFuncAttributeMaxDynamicSharedMemorySize, smem_attn);
    }

    // 0) pre-round weights to tf32 (bit-identical to in-loop cvt; x stays raw)
    {
        int n4q = 3 * DIMC * DIMC / 4;
        round_tf32_kernel<<<(n4q + 255) / 256, 256>>>(qkv_w, wq_ptr, n4q);
        int n4p = DIMC * DIMC / 4;
        round_tf32_kernel<<<(n4p + 255) / 256, 256>>>(proj_w, wp_ptr, n4p);
    }

    // 1) qkv = x @ qkv_w^T + b -> relu/pos -> g_q,g_k,g_v (head-major)
    dim3 g1(3 * DIMC / BN, MROWS / BM);   // (9, 512)
    gemm_tc_kernel<<<g1, 256, smem_gemm>>>(x, wq_ptr, qkv_b, pos, nullptr, 0);

    // 2) linear attention + depthwise conv -> g_att [M, C]
    attn_kernel<<<BHH, 256, smem_attn>>>(dwc_w, dwc_b);

    // 3) out = g_att @ proj_w^T + proj_b
    dim3 g3(DIMC / BN, MROWS / BM);       // (3, 512)
    gemm_tc_kernel<<<g3, 256, smem_gemm>>>(att_ptr, wp_ptr, proj_b, nullptr, out, 1);
}